// round 5
// baseline (speedup 1.0000x reference)
#include <cuda_runtime.h>
#include <cuda_bf16.h>
#include <math.h>

#define NN 40000
#define EE 640000
#define DD 128
#define DEE 64
#define LAMDA 0.5f
#define NEG_SLOPE 0.01f
#define FULL 0xffffffffu

// ---------------- scratch (device globals; zero-initialized at load) --------
__device__ __align__(16) float g_z[(size_t)NN * DD];     // z = node_h @ fc_w^T
__device__ float g_s[NN];                                // s_node
__device__ float g_d[NN];                                // d_node
__device__ int   g_deg[NN];                              // in-degree histogram (re-zeroed by k_scan)
__device__ int   g_off[NN + 1];                          // CSR offsets
__device__ int   g_cur[NN];                              // CSR cursors
__device__ __align__(8) uint2 g_pack[EE];                // {src, e} sorted by dst
__device__ __align__(16) float g_we[DEE];                // edge_fc_w^T @ w_e
__device__ float g_be;                                   // dot(edge_fc_b, w_e)

// ---------------- kernels ---------------------------------------------------

// projection vectors only (g_deg zeroing is handled by k_scan each call)
__global__ void k_init(const float* __restrict__ edge_fc_w,
                       const float* __restrict__ edge_fc_b,
                       const float* __restrict__ attn_w) {
    int k = threadIdx.x;
    if (k < DEE) {
        float ee = 0.f;
        for (int j = 0; j < DEE; j++)
            ee += attn_w[2 * DD + j] * edge_fc_w[j * DEE + k];
        g_we[k] = ee;
    }
    if (k == 0) {
        float b = 0.f;
        for (int j = 0; j < DEE; j++)
            b += edge_fc_b[j] * attn_w[2 * DD + j];
        g_be = b;
    }
}

// in-degree histogram (int4-vectorized dst read)
__global__ void k_hist(const int* __restrict__ dst) {
    int i = blockIdx.x * blockDim.x + threadIdx.x;
    int base = i * 4;
    if (base + 3 < EE) {
        int4 d = *(const int4*)(dst + base);
        atomicAdd(&g_deg[d.x], 1);
        atomicAdd(&g_deg[d.y], 1);
        atomicAdd(&g_deg[d.z], 1);
        atomicAdd(&g_deg[d.w], 1);
    } else {
        for (int j = base; j < EE; j++) atomicAdd(&g_deg[dst[j]], 1);
    }
}

// single-block exclusive scan of g_deg -> g_off / g_cur.
// Also re-zeroes g_deg so the next kernel_launch call starts clean
// (module load guarantees zeros on the very first call).
#define SCAN_T 1024
#define SCAN_C 40
__global__ void k_scan() {
    __shared__ int part[SCAN_T];
    int t = threadIdx.x;
    int base = t * SCAN_C;
    int local[SCAN_C];
    int s = 0;
#pragma unroll
    for (int i = 0; i < SCAN_C; i++) {
        int idx = base + i;
        int v = 0;
        if (idx < NN) {
            v = g_deg[idx];
            g_deg[idx] = 0;
        }
        local[i] = s;
        s += v;
    }
    part[t] = s;
    __syncthreads();
    for (int d = 1; d < SCAN_T; d <<= 1) {
        int v = (t >= d) ? part[t - d] : 0;
        __syncthreads();
        part[t] += v;
        __syncthreads();
    }
    int pre = (t == 0) ? 0 : part[t - 1];
#pragma unroll
    for (int i = 0; i < SCAN_C; i++) {
        int idx = base + i;
        if (idx < NN) {
            int o = pre + local[i];
            g_off[idx] = o;
            g_cur[idx] = o;
        }
    }
    if (t == SCAN_T - 1) g_off[NN] = part[SCAN_T - 1];
}

// z = node_h @ fc_w^T (128x128 tile, 512 threads, 4x8 reg blocking) + fused
// s/d epilogue. 16 warps/SM (4 per SMSP) for latency hiding.
// ZPAD must be a multiple of 4 (float4 shared loads need 16B alignment).
#define ZPAD 132
__global__ void __launch_bounds__(512, 1)
k_z(const float* __restrict__ node_h,
    const float* __restrict__ fc_w,
    const float* __restrict__ attn_w) {
    extern __shared__ float sm[];
    float* sW = sm;                 // Wt[k][j], stride ZPAD
    float* sA = sm + DD * ZPAD;     // At[k][r], stride ZPAD
    int t = threadIdx.x;
    int rowBase = blockIdx.x * 128;

    for (int p = t; p < DD * DD; p += 512) {
        int j = p >> 7, k = p & 127;
        sW[k * ZPAD + j] = fc_w[p];
    }
    for (int p = t; p < 128 * DD; p += 512) {
        int r = p >> 7, k = p & 127;
        int row = rowBase + r;
        sA[k * ZPAD + r] = (row < NN) ? node_h[(size_t)row * DD + k] : 0.f;
    }
    __syncthreads();

    int tx = t & 15, ty = t >> 4;      // tx 0..15 (cols), ty 0..31 (4 rows each)
    int c0 = tx * 4;                   // cols c0..c0+3
    int c1 = 64 + tx * 4;              // cols c1..c1+3
    int r0 = ty * 4;                   // rows r0..r0+3
    float acc[4][8];
#pragma unroll
    for (int i = 0; i < 4; i++)
#pragma unroll
        for (int j = 0; j < 8; j++) acc[i][j] = 0.f;

#pragma unroll 8
    for (int k = 0; k < DD; k++) {
        float4 a0 = *(const float4*)&sA[k * ZPAD + r0];
        float4 b0 = *(const float4*)&sW[k * ZPAD + c0];
        float4 b1 = *(const float4*)&sW[k * ZPAD + c1];
        float a[4] = {a0.x, a0.y, a0.z, a0.w};
        float b[8] = {b0.x, b0.y, b0.z, b0.w, b1.x, b1.y, b1.z, b1.w};
#pragma unroll
        for (int i = 0; i < 4; i++)
#pragma unroll
            for (int j = 0; j < 8; j++) acc[i][j] = fmaf(a[i], b[j], acc[i][j]);
    }

    // store z (two float4 groups per row)
#pragma unroll
    for (int i = 0; i < 4; i++) {
        int row = rowBase + r0 + i;
        if (row < NN) {
            float4 v0 = make_float4(acc[i][0], acc[i][1], acc[i][2], acc[i][3]);
            float4 v1 = make_float4(acc[i][4], acc[i][5], acc[i][6], acc[i][7]);
            *(float4*)&g_z[(size_t)row * DD + c0] = v0;
            *(float4*)&g_z[(size_t)row * DD + c1] = v1;
        }
    }

    // fused s/d epilogue: s[row] = sum_col z[row][col]*attn_w[col]
    float ws[8], wd[8];
#pragma unroll
    for (int j = 0; j < 4; j++) {
        ws[j]     = attn_w[c0 + j];
        ws[j + 4] = attn_w[c1 + j];
        wd[j]     = attn_w[DD + c0 + j];
        wd[j + 4] = attn_w[DD + c1 + j];
    }
#pragma unroll
    for (int i = 0; i < 4; i++) {
        float ps = 0.f, pd = 0.f;
#pragma unroll
        for (int j = 0; j < 8; j++) {
            ps = fmaf(acc[i][j], ws[j], ps);
            pd = fmaf(acc[i][j], wd[j], pd);
        }
#pragma unroll
        for (int o = 8; o > 0; o >>= 1) {
            ps += __shfl_xor_sync(FULL, ps, o);
            pd += __shfl_xor_sync(FULL, pd, o);
        }
        int row = rowBase + r0 + i;
        if (tx == 0 && row < NN) {
            g_s[row] = ps;
            g_d[row] = pd;
        }
    }
}

// edge logits + direct CSR scatter. 8 lanes per edge, 4 edges per warp.
__global__ void k_edge(const float* __restrict__ edge_h,
                       const int* __restrict__ src,
                       const int* __restrict__ dst) {
    int gw = (blockIdx.x * blockDim.x + threadIdx.x) >> 5;
    int lane = threadIdx.x & 31;
    int sub = lane >> 3;
    int l8 = lane & 7;
    long long ebase = (long long)gw * 4;
    if (ebase >= EE) return;
    int eid = (int)ebase + sub;

    float part = 0.f;
    if (eid < EE) {
        const float4* row = (const float4*)(edge_h + (size_t)eid * DEE);
        float4 v0 = row[l8];
        float4 v1 = row[l8 + 8];
        float4 w0 = ((const float4*)g_we)[l8];
        float4 w1 = ((const float4*)g_we)[l8 + 8];
        part = v0.x * w0.x + v0.y * w0.y + v0.z * w0.z + v0.w * w0.w
             + v1.x * w1.x + v1.y * w1.y + v1.z * w1.z + v1.w * w1.w;
    }
#pragma unroll
    for (int o = 4; o > 0; o >>= 1)
        part += __shfl_xor_sync(FULL, part, o);

    if (l8 == 0 && eid < EE) {
        int s = src[eid], d = dst[eid];
        float v = part + g_be + g_s[s] + g_d[d];
        v = (v > 0.f) ? v : NEG_SLOPE * v;
        int p = atomicAdd(&g_cur[d], 1);
        uint2 pk;
        pk.x = (unsigned)s;
        pk.y = __float_as_uint(v);
        g_pack[p] = pk;
    }
}

// warp per node: softmax (no max shift: logits are O(10), exp can't overflow
// fp32; alpha = ex/sum is shift-invariant) + weighted sum of z[src] + residual
__global__ void k_agg(const float* __restrict__ node_h,
                      float* __restrict__ out) {
    int n = (blockIdx.x * blockDim.x + threadIdx.x) >> 5;
    int lane = threadIdx.x & 31;
    if (n >= NN) return;

    int beg = g_off[n], end = g_off[n + 1];

    float4 acc = make_float4(0.f, 0.f, 0.f, 0.f);
    float dsum = 0.f;
    for (int b = beg; b < end; b += 32) {
        int i = b + lane;
        float ev = 0.f;
        int sv = 0;
        if (i < end) {
            uint2 p = g_pack[i];
            sv = (int)p.x;
            ev = __expf(__uint_as_float(p.y));
            dsum += ev;
        }
        int cnt = min(32, end - b);
        int j = 0;
        for (; j + 2 <= cnt; j += 2) {
            float ex0 = __shfl_sync(FULL, ev, j);
            float ex1 = __shfl_sync(FULL, ev, j + 1);
            int s0 = __shfl_sync(FULL, sv, j);
            int s1 = __shfl_sync(FULL, sv, j + 1);
            float4 z0 = ((const float4*)(g_z + (size_t)s0 * DD))[lane];
            float4 z1 = ((const float4*)(g_z + (size_t)s1 * DD))[lane];
            acc.x = fmaf(ex0, z0.x, fmaf(ex1, z1.x, acc.x));
            acc.y = fmaf(ex0, z0.y, fmaf(ex1, z1.y, acc.y));
            acc.z = fmaf(ex0, z0.z, fmaf(ex1, z1.z, acc.z));
            acc.w = fmaf(ex0, z0.w, fmaf(ex1, z1.w, acc.w));
        }
        if (j < cnt) {
            float ex = __shfl_sync(FULL, ev, j);
            int s = __shfl_sync(FULL, sv, j);
            float4 zv = ((const float4*)(g_z + (size_t)s * DD))[lane];
            acc.x = fmaf(ex, zv.x, acc.x);
            acc.y = fmaf(ex, zv.y, acc.y);
            acc.z = fmaf(ex, zv.z, acc.z);
            acc.w = fmaf(ex, zv.w, acc.w);
        }
    }
#pragma unroll
    for (int o = 16; o > 0; o >>= 1)
        dsum += __shfl_xor_sync(FULL, dsum, o);

    float inv = (end > beg) ? (LAMDA / dsum) : 0.f;
    float4 nh = ((const float4*)(node_h + (size_t)n * DD))[lane];
    float4 r;
    r.x = (1.f - LAMDA) * nh.x + inv * acc.x;
    r.y = (1.f - LAMDA) * nh.y + inv * acc.y;
    r.z = (1.f - LAMDA) * nh.z + inv * acc.z;
    r.w = (1.f - LAMDA) * nh.w + inv * acc.w;
    ((float4*)(out + (size_t)n * DD))[lane] = r;
}

// ---------------- launch -----------------------------------------------------

extern "C" void kernel_launch(void* const* d_in, const int* in_sizes, int n_in,
                              void* d_out, int out_size) {
    const float* node_h    = (const float*)d_in[0];
    const float* edge_h    = (const float*)d_in[1];
    const int*   src       = (const int*)d_in[2];
    const int*   dst       = (const int*)d_in[3];
    const float* fc_w      = (const float*)d_in[4];
    const float* edge_fc_w = (const float*)d_in[5];
    const float* edge_fc_b = (const float*)d_in[6];
    const float* attn_w    = (const float*)d_in[7];
    float* out = (float*)d_out;

    static bool attr_set = false;
    if (!attr_set) {
        cudaFuncSetAttribute(k_z, cudaFuncAttributeMaxDynamicSharedMemorySize,
                             2 * DD * ZPAD * (int)sizeof(float));
        attr_set = true;
    }

    k_init<<<1, 64>>>(edge_fc_w, edge_fc_b, attn_w);
    k_hist<<<(EE / 4 + 255) / 256, 256>>>(dst);
    k_scan<<<1, SCAN_T>>>();
    k_z<<<(NN + 127) / 128, 512, 2 * DD * ZPAD * (int)sizeof(float)>>>(node_h, fc_w, attn_w);
    // warp = 4 edges, block = 32 edges
    k_edge<<<(EE + 31) / 32, 256>>>(edge_h, src, dst);
    k_agg<<<(NN * 32 + 255) / 256, 256>>>(node_h, out);
}

// round 7
// speedup vs baseline: 1.1368x; 1.1368x over previous
#include <cuda_runtime.h>
#include <cuda_bf16.h>
#include <math.h>
#include <stdint.h>

#define NN 40000
#define EE 640000
#define DD 128
#define DEE 64
#define LAMDA 0.5f
#define NEG_SLOPE 0.01f
#define FULL 0xffffffffu

// ---------------- scratch (device globals; zero-initialized at load) --------
__device__ __align__(16) float g_z[(size_t)NN * DD];     // z = node_h @ fc_w^T
__device__ float g_s[NN];                                // s_node
__device__ float g_d[NN];                                // d_node
__device__ int   g_deg[NN];                              // in-degree histogram (re-zeroed by k_scan)
__device__ int   g_off[NN + 1];                          // CSR offsets
__device__ int   g_cur[NN];                              // CSR cursors
__device__ __align__(8) uint2 g_pack[EE];                // {src, e} sorted by dst
__device__ __align__(16) float g_we[DEE];                // edge_fc_w^T @ w_e
__device__ float g_be;                                   // dot(edge_fc_b, w_e)
// packed W fragments: idx = n*32 + kk*4 + q -> {bh0, bh1, bl0, bl1}
__device__ __align__(16) uint4 g_wp[DD * 32];

// ---------------- helpers ----------------------------------------------------
static __device__ __forceinline__ uint32_t packbf(__nv_bfloat16 a, __nv_bfloat16 b) {
    __nv_bfloat162 p = __halves2bfloat162(a, b);
    return *(uint32_t*)&p;
}

// D(16x8,f32) += A(16x16,bf16,row) * B(16x8,bf16,col)
static __device__ __forceinline__ void mma16816(float* c,
                                                uint32_t a0, uint32_t a1,
                                                uint32_t a2, uint32_t a3,
                                                uint32_t b0, uint32_t b1) {
    asm volatile(
        "mma.sync.aligned.m16n8k16.row.col.f32.bf16.bf16.f32 "
        "{%0,%1,%2,%3}, {%4,%5,%6,%7}, {%8,%9}, {%0,%1,%2,%3};"
        : "+f"(c[0]), "+f"(c[1]), "+f"(c[2]), "+f"(c[3])
        : "r"(a0), "r"(a1), "r"(a2), "r"(a3), "r"(b0), "r"(b1));
}

// ---------------- kernels ---------------------------------------------------

// block 0: projection vectors; blocks 1..16: pack fc_w into bf16 hi/lo frags
__global__ void k_init(const float* __restrict__ fc_w,
                       const float* __restrict__ edge_fc_w,
                       const float* __restrict__ edge_fc_b,
                       const float* __restrict__ attn_w) {
    int b = blockIdx.x, t = threadIdx.x;
    if (b == 0) {
        if (t < DEE) {
            float ee = 0.f;
            for (int j = 0; j < DEE; j++)
                ee += attn_w[2 * DD + j] * edge_fc_w[j * DEE + t];
            g_we[t] = ee;
        }
        if (t == 0) {
            float bb = 0.f;
            for (int j = 0; j < DEE; j++)
                bb += edge_fc_b[j] * attn_w[2 * DD + j];
            g_be = bb;
        }
    } else {
        int idx = (b - 1) * 256 + t;          // 0..4095
        int n = idx >> 5, rem = idx & 31;
        int kk = rem >> 2, q = rem & 3;
        int k0 = kk * 16 + q * 2;
        const float* wr = fc_w + (size_t)n * DD;
        float x0 = wr[k0], x1 = wr[k0 + 1], x8 = wr[k0 + 8], x9 = wr[k0 + 9];
        __nv_bfloat16 h0 = __float2bfloat16(x0), h1 = __float2bfloat16(x1);
        __nv_bfloat16 h8 = __float2bfloat16(x8), h9 = __float2bfloat16(x9);
        uint4 v;
        v.x = packbf(h0, h1);
        v.y = packbf(h8, h9);
        v.z = packbf(__float2bfloat16(x0 - __bfloat162float(h0)),
                     __float2bfloat16(x1 - __bfloat162float(h1)));
        v.w = packbf(__float2bfloat16(x8 - __bfloat162float(h8)),
                     __float2bfloat16(x9 - __bfloat162float(h9)));
        g_wp[idx] = v;
    }
}

// in-degree histogram (int4-vectorized dst read)
__global__ void k_hist(const int* __restrict__ dst) {
    int i = blockIdx.x * blockDim.x + threadIdx.x;
    int base = i * 4;
    if (base + 3 < EE) {
        int4 d = *(const int4*)(dst + base);
        atomicAdd(&g_deg[d.x], 1);
        atomicAdd(&g_deg[d.y], 1);
        atomicAdd(&g_deg[d.z], 1);
        atomicAdd(&g_deg[d.w], 1);
    } else {
        for (int j = base; j < EE; j++) atomicAdd(&g_deg[dst[j]], 1);
    }
}

// single-block exclusive scan of g_deg -> g_off / g_cur; re-zeroes g_deg.
#define SCAN_T 1024
#define SCAN_C 40
__global__ void k_scan() {
    __shared__ int part[SCAN_T];
    int t = threadIdx.x;
    int base = t * SCAN_C;
    int local[SCAN_C];
    int s = 0;
#pragma unroll
    for (int i = 0; i < SCAN_C; i++) {
        int idx = base + i;
        int v = 0;
        if (idx < NN) {
            v = g_deg[idx];
            g_deg[idx] = 0;
        }
        local[i] = s;
        s += v;
    }
    part[t] = s;
    __syncthreads();
    for (int d = 1; d < SCAN_T; d <<= 1) {
        int v = (t >= d) ? part[t - d] : 0;
        __syncthreads();
        part[t] += v;
        __syncthreads();
    }
    int pre = (t == 0) ? 0 : part[t - 1];
#pragma unroll
    for (int i = 0; i < SCAN_C; i++) {
        int idx = base + i;
        if (idx < NN) {
            int o = pre + local[i];
            g_off[idx] = o;
            g_cur[idx] = o;
        }
    }
    if (t == SCAN_T - 1) g_off[NN] = part[SCAN_T - 1];
}

// ---------------- k_z: HMMA 3xbf16 GEMM -------------------------------------
// z = node_h @ fc_w^T, fp32 via A_hi*W_hi + A_lo*W_hi + A_hi*W_lo.
// CTA = 128 rows, 8 warps, warp = 16 rows x 128 cols, mma.m16n8k16.
// A staged in smem as interleaved {hi2, lo2} uint2, stride SAP=68 (bank-clean).
#define SAP 68

__global__ void __launch_bounds__(256, 2)
k_z(const float* __restrict__ node_h,
    const float* __restrict__ attn_w) {
    extern __shared__ uint2 sA[];   // [128][SAP]
    int t = threadIdx.x;
    int w = t >> 5, lane = t & 31;
    int q = lane & 3, rr = lane >> 2;
    int rowBase = blockIdx.x * 128;

    // stage A as bf16 hi/lo
    for (int p = t; p < 128 * 32; p += 256) {
        int row = p >> 5, g = p & 31;
        int gr = rowBase + row;
        float4 v = (gr < NN) ? __ldg(&((const float4*)node_h)[(size_t)gr * 32 + g])
                             : make_float4(0.f, 0.f, 0.f, 0.f);
        __nv_bfloat16 h0 = __float2bfloat16(v.x), h1 = __float2bfloat16(v.y);
        __nv_bfloat16 h2 = __float2bfloat16(v.z), h3 = __float2bfloat16(v.w);
        uint2 e0, e1;
        e0.x = packbf(h0, h1);
        e0.y = packbf(__float2bfloat16(v.x - __bfloat162float(h0)),
                      __float2bfloat16(v.y - __bfloat162float(h1)));
        e1.x = packbf(h2, h3);
        e1.y = packbf(__float2bfloat16(v.z - __bfloat162float(h2)),
                      __float2bfloat16(v.w - __bfloat162float(h3)));
        sA[row * SAP + 2 * g] = e0;
        sA[row * SAP + 2 * g + 1] = e1;
    }
    __syncthreads();

    float acc[16][4];
#pragma unroll
    for (int i = 0; i < 16; i++)
        acc[i][0] = acc[i][1] = acc[i][2] = acc[i][3] = 0.f;

    int ra = w * 16 + rr;     // tile-local fragment row
#pragma unroll
    for (int kk = 0; kk < 8; kk++) {
        int cp = kk * 8 + q;  // column-pair index
        uint2 f0 = sA[ra * SAP + cp];
        uint2 f1 = sA[(ra + 8) * SAP + cp];
        uint2 f2 = sA[ra * SAP + cp + 4];
        uint2 f3 = sA[(ra + 8) * SAP + cp + 4];
#pragma unroll
        for (int nt = 0; nt < 16; nt++) {
            int n = nt * 8 + rr;
            uint4 bb = __ldg(&g_wp[n * 32 + kk * 4 + q]);
            mma16816(acc[nt], f0.x, f1.x, f2.x, f3.x, bb.x, bb.y);  // Ah*Wh
            mma16816(acc[nt], f0.y, f1.y, f2.y, f3.y, bb.x, bb.y);  // Al*Wh
            mma16816(acc[nt], f0.x, f1.x, f2.x, f3.x, bb.z, bb.w);  // Ah*Wl
        }
    }

    // epilogue: z store + fused s/d dots
    int row0 = rowBase + ra, row1 = row0 + 8;
    float psl = 0.f, psh = 0.f, pdl = 0.f, pdh = 0.f;
#pragma unroll
    for (int nt = 0; nt < 16; nt++) {
        int c = nt * 8 + q * 2;
        float w0s = __ldg(&attn_w[c]), w1s = __ldg(&attn_w[c + 1]);
        float w0d = __ldg(&attn_w[DD + c]), w1d = __ldg(&attn_w[DD + c + 1]);
        psl = fmaf(acc[nt][0], w0s, fmaf(acc[nt][1], w1s, psl));
        psh = fmaf(acc[nt][2], w0s, fmaf(acc[nt][3], w1s, psh));
        pdl = fmaf(acc[nt][0], w0d, fmaf(acc[nt][1], w1d, pdl));
        pdh = fmaf(acc[nt][2], w0d, fmaf(acc[nt][3], w1d, pdh));
        if (row0 < NN)
            *(float2*)&g_z[(size_t)row0 * DD + c] = make_float2(acc[nt][0], acc[nt][1]);
        if (row1 < NN)
            *(float2*)&g_z[(size_t)row1 * DD + c] = make_float2(acc[nt][2], acc[nt][3]);
    }
    psl += __shfl_xor_sync(FULL, psl, 1); psl += __shfl_xor_sync(FULL, psl, 2);
    psh += __shfl_xor_sync(FULL, psh, 1); psh += __shfl_xor_sync(FULL, psh, 2);
    pdl += __shfl_xor_sync(FULL, pdl, 1); pdl += __shfl_xor_sync(FULL, pdl, 2);
    pdh += __shfl_xor_sync(FULL, pdh, 1); pdh += __shfl_xor_sync(FULL, pdh, 2);
    if (q == 0) {
        if (row0 < NN) { g_s[row0] = psl; g_d[row0] = pdl; }
        if (row1 < NN) { g_s[row1] = psh; g_d[row1] = pdh; }
    }
}

// edge logits + direct CSR scatter. 8 lanes per edge, 4 edges per warp.
__global__ void k_edge(const float* __restrict__ edge_h,
                       const int* __restrict__ src,
                       const int* __restrict__ dst) {
    int gw = (blockIdx.x * blockDim.x + threadIdx.x) >> 5;
    int lane = threadIdx.x & 31;
    int sub = lane >> 3;
    int l8 = lane & 7;
    long long ebase = (long long)gw * 4;
    if (ebase >= EE) return;
    int eid = (int)ebase + sub;

    float part = 0.f;
    if (eid < EE) {
        const float4* row = (const float4*)(edge_h + (size_t)eid * DEE);
        float4 v0 = row[l8];
        float4 v1 = row[l8 + 8];
        float4 w0 = ((const float4*)g_we)[l8];
        float4 w1 = ((const float4*)g_we)[l8 + 8];
        part = v0.x * w0.x + v0.y * w0.y + v0.z * w0.z + v0.w * w0.w
             + v1.x * w1.x + v1.y * w1.y + v1.z * w1.z + v1.w * w1.w;
    }
#pragma unroll
    for (int o = 4; o > 0; o >>= 1)
        part += __shfl_xor_sync(FULL, part, o);

    if (l8 == 0 && eid < EE) {
        int s = src[eid], d = dst[eid];
        float v = part + g_be + g_s[s] + g_d[d];
        v = (v > 0.f) ? v : NEG_SLOPE * v;
        int p = atomicAdd(&g_cur[d], 1);
        uint2 pk;
        pk.x = (unsigned)s;
        pk.y = __float_as_uint(v);
        g_pack[p] = pk;
    }
}

// warp per node: softmax (shift-free; logits are O(10)) + weighted z[src] sum
__global__ void k_agg(const float* __restrict__ node_h,
                      float* __restrict__ out) {
    int n = (blockIdx.x * blockDim.x + threadIdx.x) >> 5;
    int lane = threadIdx.x & 31;
    if (n >= NN) return;

    int beg = g_off[n], end = g_off[n + 1];

    float4 acc = make_float4(0.f, 0.f, 0.f, 0.f);
    float dsum = 0.f;
    for (int b = beg; b < end; b += 32) {
        int i = b + lane;
        float ev = 0.f;
        int sv = 0;
        if (i < end) {
            uint2 p = g_pack[i];
            sv = (int)p.x;
            ev = __expf(__uint_as_float(p.y));
            dsum += ev;
        }
        int cnt = min(32, end - b);
        int j = 0;
        for (; j + 2 <= cnt; j += 2) {
            float ex0 = __shfl_sync(FULL, ev, j);
            float ex1 = __shfl_sync(FULL, ev, j + 1);
            int s0 = __shfl_sync(FULL, sv, j);
            int s1 = __shfl_sync(FULL, sv, j + 1);
            float4 z0 = ((const float4*)(g_z + (size_t)s0 * DD))[lane];
            float4 z1 = ((const float4*)(g_z + (size_t)s1 * DD))[lane];
            acc.x = fmaf(ex0, z0.x, fmaf(ex1, z1.x, acc.x));
            acc.y = fmaf(ex0, z0.y, fmaf(ex1, z1.y, acc.y));
            acc.z = fmaf(ex0, z0.z, fmaf(ex1, z1.z, acc.z));
            acc.w = fmaf(ex0, z0.w, fmaf(ex1, z1.w, acc.w));
        }
        if (j < cnt) {
            float ex = __shfl_sync(FULL, ev, j);
            int s = __shfl_sync(FULL, sv, j);
            float4 zv = ((const float4*)(g_z + (size_t)s * DD))[lane];
            acc.x = fmaf(ex, zv.x, acc.x);
            acc.y = fmaf(ex, zv.y, acc.y);
            acc.z = fmaf(ex, zv.z, acc.z);
            acc.w = fmaf(ex, zv.w, acc.w);
        }
    }
#pragma unroll
    for (int o = 16; o > 0; o >>= 1)
        dsum += __shfl_xor_sync(FULL, dsum, o);

    float inv = (end > beg) ? (LAMDA / dsum) : 0.f;
    float4 nh = ((const float4*)(node_h + (size_t)n * DD))[lane];
    float4 r;
    r.x = (1.f - LAMDA) * nh.x + inv * acc.x;
    r.y = (1.f - LAMDA) * nh.y + inv * acc.y;
    r.z = (1.f - LAMDA) * nh.z + inv * acc.z;
    r.w = (1.f - LAMDA) * nh.w + inv * acc.w;
    ((float4*)(out + (size_t)n * DD))[lane] = r;
}

// ---------------- launch -----------------------------------------------------

extern "C" void kernel_launch(void* const* d_in, const int* in_sizes, int n_in,
                              void* d_out, int out_size) {
    const float* node_h    = (const float*)d_in[0];
    const float* edge_h    = (const float*)d_in[1];
    const int*   src       = (const int*)d_in[2];
    const int*   dst       = (const int*)d_in[3];
    const float* fc_w      = (const float*)d_in[4];
    const float* edge_fc_w = (const float*)d_in[5];
    const float* edge_fc_b = (const float*)d_in[6];
    const float* attn_w    = (const float*)d_in[7];
    float* out = (float*)d_out;

    const int kz_smem = 128 * SAP * (int)sizeof(uint2);   // 69632 B

    static bool attr_set = false;
    if (!attr_set) {
        cudaFuncSetAttribute(k_z, cudaFuncAttributeMaxDynamicSharedMemorySize, kz_smem);
        attr_set = true;
    }

    k_init<<<17, 256>>>(fc_w, edge_fc_w, edge_fc_b, attn_w);
    k_hist<<<(EE / 4 + 255) / 256, 256>>>(dst);
    k_scan<<<1, SCAN_T>>>();
    k_z<<<(NN + 127) / 128, 256, kz_smem>>>(node_h, attn_w);
    // warp = 4 edges, block = 32 edges
    k_edge<<<(EE + 31) / 32, 256>>>(edge_h, src, dst);
    k_agg<<<(NN * 32 + 255) / 256, 256>>>(node_h, out);
}

// round 8
// speedup vs baseline: 1.3593x; 1.1957x over previous
#include <cuda_runtime.h>
#include <cuda_bf16.h>
#include <math.h>
#include <stdint.h>

#define NN 40000
#define EE 640000
#define DD 128
#define DEE 64
#define LAMDA 0.5f
#define NEG_SLOPE 0.01f
#define FULL 0xffffffffu

// ---------------- scratch (device globals; zero-initialized at load) --------
__device__ __align__(16) float g_z[(size_t)NN * DD];     // z = node_h @ fc_w^T
__device__ float g_s[NN];                                // s_node
__device__ float g_d[NN];                                // d_node
__device__ int   g_deg[NN];                              // in-degree histogram (re-zeroed by k_scan)
__device__ int   g_off[NN + 1];                          // CSR offsets
__device__ int   g_cur[NN];                              // CSR cursors
__device__ __align__(8) uint2 g_pack[EE];                // {src, e} sorted by dst
__device__ __align__(16) float g_we[DEE];                // edge_fc_w^T @ w_e
__device__ float g_be;                                   // dot(edge_fc_b, w_e)
// packed W fragments, coalesced layout:
//   g_wp[kk*512 + (n>>3)*32 + (n&7)*4 + q] = frag(n, kk, q) = {bh0,bh1,bl0,bl1}
__device__ __align__(16) uint4 g_wp[DD * 32];

// ---------------- helpers ----------------------------------------------------
static __device__ __forceinline__ uint32_t packbf(__nv_bfloat16 a, __nv_bfloat16 b) {
    __nv_bfloat162 p = __halves2bfloat162(a, b);
    return *(uint32_t*)&p;
}

// D(16x8,f32) += A(16x16,bf16,row) * B(16x8,bf16,col)
static __device__ __forceinline__ void mma16816(float* c,
                                                uint32_t a0, uint32_t a1,
                                                uint32_t a2, uint32_t a3,
                                                uint32_t b0, uint32_t b1) {
    asm volatile(
        "mma.sync.aligned.m16n8k16.row.col.f32.bf16.bf16.f32 "
        "{%0,%1,%2,%3}, {%4,%5,%6,%7}, {%8,%9}, {%0,%1,%2,%3};"
        : "+f"(c[0]), "+f"(c[1]), "+f"(c[2]), "+f"(c[3])
        : "r"(a0), "r"(a1), "r"(a2), "r"(a3), "r"(b0), "r"(b1));
}

// ---------------- kernels ---------------------------------------------------

// block 0: projection vectors; blocks 1..16: pack fc_w into bf16 hi/lo frags
__global__ void k_init(const float* __restrict__ fc_w,
                       const float* __restrict__ edge_fc_w,
                       const float* __restrict__ edge_fc_b,
                       const float* __restrict__ attn_w) {
    int b = blockIdx.x, t = threadIdx.x;
    if (b == 0) {
        if (t < DEE) {
            float ee = 0.f;
            for (int j = 0; j < DEE; j++)
                ee += attn_w[2 * DD + j] * edge_fc_w[j * DEE + t];
            g_we[t] = ee;
        }
        if (t == 0) {
            float bb = 0.f;
            for (int j = 0; j < DEE; j++)
                bb += edge_fc_b[j] * attn_w[2 * DD + j];
            g_be = bb;
        }
    } else {
        int idx = (b - 1) * 256 + t;          // 0..4095
        int n = idx >> 5, rem = idx & 31;
        int kk = rem >> 2, q = rem & 3;
        int k0 = kk * 16 + q * 2;
        const float* wr = fc_w + (size_t)n * DD;
        float x0 = wr[k0], x1 = wr[k0 + 1], x8 = wr[k0 + 8], x9 = wr[k0 + 9];
        __nv_bfloat16 h0 = __float2bfloat16(x0), h1 = __float2bfloat16(x1);
        __nv_bfloat16 h8 = __float2bfloat16(x8), h9 = __float2bfloat16(x9);
        uint4 v;
        v.x = packbf(h0, h1);
        v.y = packbf(h8, h9);
        v.z = packbf(__float2bfloat16(x0 - __bfloat162float(h0)),
                     __float2bfloat16(x1 - __bfloat162float(h1)));
        v.w = packbf(__float2bfloat16(x8 - __bfloat162float(h8)),
                     __float2bfloat16(x9 - __bfloat162float(h9)));
        g_wp[kk * 512 + (n >> 3) * 32 + (n & 7) * 4 + q] = v;
    }
}

// in-degree histogram (int4-vectorized dst read)
__global__ void k_hist(const int* __restrict__ dst) {
    int i = blockIdx.x * blockDim.x + threadIdx.x;
    int base = i * 4;
    if (base + 3 < EE) {
        int4 d = *(const int4*)(dst + base);
        atomicAdd(&g_deg[d.x], 1);
        atomicAdd(&g_deg[d.y], 1);
        atomicAdd(&g_deg[d.z], 1);
        atomicAdd(&g_deg[d.w], 1);
    } else {
        for (int j = base; j < EE; j++) atomicAdd(&g_deg[dst[j]], 1);
    }
}

// single-block exclusive scan of g_deg -> g_off / g_cur; re-zeroes g_deg.
#define SCAN_T 1024
#define SCAN_C 40
__global__ void k_scan() {
    __shared__ int part[SCAN_T];
    int t = threadIdx.x;
    int base = t * SCAN_C;
    int local[SCAN_C];
    int s = 0;
#pragma unroll
    for (int i = 0; i < SCAN_C; i++) {
        int idx = base + i;
        int v = 0;
        if (idx < NN) {
            v = g_deg[idx];
            g_deg[idx] = 0;
        }
        local[i] = s;
        s += v;
    }
    part[t] = s;
    __syncthreads();
    for (int d = 1; d < SCAN_T; d <<= 1) {
        int v = (t >= d) ? part[t - d] : 0;
        __syncthreads();
        part[t] += v;
        __syncthreads();
    }
    int pre = (t == 0) ? 0 : part[t - 1];
#pragma unroll
    for (int i = 0; i < SCAN_C; i++) {
        int idx = base + i;
        if (idx < NN) {
            int o = pre + local[i];
            g_off[idx] = o;
            g_cur[idx] = o;
        }
    }
    if (t == SCAN_T - 1) g_off[NN] = part[SCAN_T - 1];
}

// ---------------- k_z: HMMA 3xbf16 GEMM -------------------------------------
// z = node_h @ fc_w^T, fp32 via A_hi*W_hi + A_lo*W_hi + A_hi*W_lo.
// CTA = 128 rows, 8 warps: warp (wm, wn) = 64 rows x 32 cols. mma.m16n8k16.
// B loads fully coalesced from g_wp (idx = kk*512 + nb*32 + lane).
#define SAP 68
#define KZ_SMEM (128 * SAP * 8 + 2 * 4 * 128 * 4)

__global__ void __launch_bounds__(256, 2)
k_z(const float* __restrict__ node_h,
    const float* __restrict__ attn_w) {
    extern __shared__ char smraw[];
    uint2* sA = (uint2*)smraw;                        // [128][SAP]
    float* sRs = (float*)(smraw + 128 * SAP * 8);     // [4 wn][128 rows]
    float* sRd = sRs + 4 * 128;
    int t = threadIdx.x;
    int w = t >> 5, lane = t & 31;
    int q = lane & 3, rr = lane >> 2;
    int wm = w & 1, wn = w >> 1;
    int rowBase = blockIdx.x * 128;

    // stage A as bf16 hi/lo (interleaved uint2)
    for (int p = t; p < 128 * 32; p += 256) {
        int row = p >> 5, g = p & 31;
        int gr = rowBase + row;
        float4 v = (gr < NN) ? __ldg(&((const float4*)node_h)[(size_t)gr * 32 + g])
                             : make_float4(0.f, 0.f, 0.f, 0.f);
        __nv_bfloat16 h0 = __float2bfloat16(v.x), h1 = __float2bfloat16(v.y);
        __nv_bfloat16 h2 = __float2bfloat16(v.z), h3 = __float2bfloat16(v.w);
        uint2 e0, e1;
        e0.x = packbf(h0, h1);
        e0.y = packbf(__float2bfloat16(v.x - __bfloat162float(h0)),
                      __float2bfloat16(v.y - __bfloat162float(h1)));
        e1.x = packbf(h2, h3);
        e1.y = packbf(__float2bfloat16(v.z - __bfloat162float(h2)),
                      __float2bfloat16(v.w - __bfloat162float(h3)));
        sA[row * SAP + 2 * g] = e0;
        sA[row * SAP + 2 * g + 1] = e1;
    }
    __syncthreads();

    float acc[4][4][4];
#pragma unroll
    for (int nt = 0; nt < 4; nt++)
#pragma unroll
        for (int mt = 0; mt < 4; mt++)
            acc[nt][mt][0] = acc[nt][mt][1] = acc[nt][mt][2] = acc[nt][mt][3] = 0.f;

#pragma unroll
    for (int kk = 0; kk < 8; kk++) {
        uint4 bb[4];
#pragma unroll
        for (int nt = 0; nt < 4; nt++)
            bb[nt] = __ldg(&g_wp[kk * 512 + (wn * 4 + nt) * 32 + lane]);
        int cp = kk * 8 + q;
#pragma unroll
        for (int mt = 0; mt < 4; mt++) {
            int rm = wm * 64 + mt * 16 + rr;
            uint2 f0 = sA[rm * SAP + cp];
            uint2 f1 = sA[(rm + 8) * SAP + cp];
            uint2 f2 = sA[rm * SAP + cp + 4];
            uint2 f3 = sA[(rm + 8) * SAP + cp + 4];
#pragma unroll
            for (int nt = 0; nt < 4; nt++) {
                mma16816(acc[nt][mt], f0.x, f1.x, f2.x, f3.x, bb[nt].x, bb[nt].y);
                mma16816(acc[nt][mt], f0.y, f1.y, f2.y, f3.y, bb[nt].x, bb[nt].y);
                mma16816(acc[nt][mt], f0.x, f1.x, f2.x, f3.x, bb[nt].z, bb[nt].w);
            }
        }
    }

    // epilogue: z store + per-warp s/d partials over this warp's 32 cols
    float wgt[4][4];   // [nt] {ws0, ws1, wd0, wd1}
#pragma unroll
    for (int nt = 0; nt < 4; nt++) {
        int c = wn * 32 + nt * 8 + q * 2;
        wgt[nt][0] = __ldg(&attn_w[c]);
        wgt[nt][1] = __ldg(&attn_w[c + 1]);
        wgt[nt][2] = __ldg(&attn_w[DD + c]);
        wgt[nt][3] = __ldg(&attn_w[DD + c + 1]);
    }
#pragma unroll
    for (int mt = 0; mt < 4; mt++) {
        int rloc0 = wm * 64 + mt * 16 + rr;
        int rloc1 = rloc0 + 8;
        int row0 = rowBase + rloc0, row1 = rowBase + rloc1;
        float psl = 0.f, psh = 0.f, pdl = 0.f, pdh = 0.f;
#pragma unroll
        for (int nt = 0; nt < 4; nt++) {
            int c = wn * 32 + nt * 8 + q * 2;
            psl = fmaf(acc[nt][mt][0], wgt[nt][0], fmaf(acc[nt][mt][1], wgt[nt][1], psl));
            psh = fmaf(acc[nt][mt][2], wgt[nt][0], fmaf(acc[nt][mt][3], wgt[nt][1], psh));
            pdl = fmaf(acc[nt][mt][0], wgt[nt][2], fmaf(acc[nt][mt][1], wgt[nt][3], pdl));
            pdh = fmaf(acc[nt][mt][2], wgt[nt][2], fmaf(acc[nt][mt][3], wgt[nt][3], pdh));
            if (row0 < NN)
                *(float2*)&g_z[(size_t)row0 * DD + c] = make_float2(acc[nt][mt][0], acc[nt][mt][1]);
            if (row1 < NN)
                *(float2*)&g_z[(size_t)row1 * DD + c] = make_float2(acc[nt][mt][2], acc[nt][mt][3]);
        }
        // reduce across q (lane bits 0-1)
        psl += __shfl_xor_sync(FULL, psl, 1); psl += __shfl_xor_sync(FULL, psl, 2);
        psh += __shfl_xor_sync(FULL, psh, 1); psh += __shfl_xor_sync(FULL, psh, 2);
        pdl += __shfl_xor_sync(FULL, pdl, 1); pdl += __shfl_xor_sync(FULL, pdl, 2);
        pdh += __shfl_xor_sync(FULL, pdh, 1); pdh += __shfl_xor_sync(FULL, pdh, 2);
        if (q == 0) {
            sRs[wn * 128 + rloc0] = psl;
            sRs[wn * 128 + rloc1] = psh;
            sRd[wn * 128 + rloc0] = pdl;
            sRd[wn * 128 + rloc1] = pdh;
        }
    }
    __syncthreads();

    // combine the 4 wn partials -> full 128-col dots
    if (t < 128) {
        int row = rowBase + t;
        if (row < NN)
            g_s[row] = sRs[t] + sRs[128 + t] + sRs[256 + t] + sRs[384 + t];
    } else {
        int r = t - 128;
        int row = rowBase + r;
        if (row < NN)
            g_d[row] = sRd[r] + sRd[128 + r] + sRd[256 + r] + sRd[384 + r];
    }
}

// edge logits + direct CSR scatter. 8 lanes per edge, 4 edges per warp.
__global__ void k_edge(const float* __restrict__ edge_h,
                       const int* __restrict__ src,
                       const int* __restrict__ dst) {
    int gw = (blockIdx.x * blockDim.x + threadIdx.x) >> 5;
    int lane = threadIdx.x & 31;
    int sub = lane >> 3;
    int l8 = lane & 7;
    long long ebase = (long long)gw * 4;
    if (ebase >= EE) return;
    int eid = (int)ebase + sub;

    float part = 0.f;
    if (eid < EE) {
        const float4* row = (const float4*)(edge_h + (size_t)eid * DEE);
        float4 v0 = row[l8];
        float4 v1 = row[l8 + 8];
        float4 w0 = ((const float4*)g_we)[l8];
        float4 w1 = ((const float4*)g_we)[l8 + 8];
        part = v0.x * w0.x + v0.y * w0.y + v0.z * w0.z + v0.w * w0.w
             + v1.x * w1.x + v1.y * w1.y + v1.z * w1.z + v1.w * w1.w;
    }
#pragma unroll
    for (int o = 4; o > 0; o >>= 1)
        part += __shfl_xor_sync(FULL, part, o);

    if (l8 == 0 && eid < EE) {
        int s = src[eid], d = dst[eid];
        float v = part + g_be + g_s[s] + g_d[d];
        v = (v > 0.f) ? v : NEG_SLOPE * v;
        int p = atomicAdd(&g_cur[d], 1);
        uint2 pk;
        pk.x = (unsigned)s;
        pk.y = __float_as_uint(v);
        g_pack[p] = pk;
    }
}

// warp per node: softmax (shift-free; logits are O(10)) + weighted z[src] sum
__global__ void k_agg(const float* __restrict__ node_h,
                      float* __restrict__ out) {
    int n = (blockIdx.x * blockDim.x + threadIdx.x) >> 5;
    int lane = threadIdx.x & 31;
    if (n >= NN) return;

    int beg = g_off[n], end = g_off[n + 1];

    float4 acc = make_float4(0.f, 0.f, 0.f, 0.f);
    float dsum = 0.f;
    for (int b = beg; b < end; b += 32) {
        int i = b + lane;
        float ev = 0.f;
        int sv = 0;
        if (i < end) {
            uint2 p = g_pack[i];
            sv = (int)p.x;
            ev = __expf(__uint_as_float(p.y));
            dsum += ev;
        }
        int cnt = min(32, end - b);
        int j = 0;
        for (; j + 2 <= cnt; j += 2) {
            float ex0 = __shfl_sync(FULL, ev, j);
            float ex1 = __shfl_sync(FULL, ev, j + 1);
            int s0 = __shfl_sync(FULL, sv, j);
            int s1 = __shfl_sync(FULL, sv, j + 1);
            float4 z0 = ((const float4*)(g_z + (size_t)s0 * DD))[lane];
            float4 z1 = ((const float4*)(g_z + (size_t)s1 * DD))[lane];
            acc.x = fmaf(ex0, z0.x, fmaf(ex1, z1.x, acc.x));
            acc.y = fmaf(ex0, z0.y, fmaf(ex1, z1.y, acc.y));
            acc.z = fmaf(ex0, z0.z, fmaf(ex1, z1.z, acc.z));
            acc.w = fmaf(ex0, z0.w, fmaf(ex1, z1.w, acc.w));
        }
        if (j < cnt) {
            float ex = __shfl_sync(FULL, ev, j);
            int s = __shfl_sync(FULL, sv, j);
            float4 zv = ((const float4*)(g_z + (size_t)s * DD))[lane];
            acc.x = fmaf(ex, zv.x, acc.x);
            acc.y = fmaf(ex, zv.y, acc.y);
            acc.z = fmaf(ex, zv.z, acc.z);
            acc.w = fmaf(ex, zv.w, acc.w);
        }
    }
#pragma unroll
    for (int o = 16; o > 0; o >>= 1)
        dsum += __shfl_xor_sync(FULL, dsum, o);

    float inv = (end > beg) ? (LAMDA / dsum) : 0.f;
    float4 nh = ((const float4*)(node_h + (size_t)n * DD))[lane];
    float4 r;
    r.x = (1.f - LAMDA) * nh.x + inv * acc.x;
    r.y = (1.f - LAMDA) * nh.y + inv * acc.y;
    r.z = (1.f - LAMDA) * nh.z + inv * acc.z;
    r.w = (1.f - LAMDA) * nh.w + inv * acc.w;
    ((float4*)(out + (size_t)n * DD))[lane] = r;
}

// ---------------- launch -----------------------------------------------------

extern "C" void kernel_launch(void* const* d_in, const int* in_sizes, int n_in,
                              void* d_out, int out_size) {
    const float* node_h    = (const float*)d_in[0];
    const float* edge_h    = (const float*)d_in[1];
    const int*   src       = (const int*)d_in[2];
    const int*   dst       = (const int*)d_in[3];
    const float* fc_w      = (const float*)d_in[4];
    const float* edge_fc_w = (const float*)d_in[5];
    const float* edge_fc_b = (const float*)d_in[6];
    const float* attn_w    = (const float*)d_in[7];
    float* out = (float*)d_out;

    static cudaStream_t s2 = nullptr;
    static cudaEvent_t evF = nullptr, evJ = nullptr;
    if (!s2) {
        cudaFuncSetAttribute(k_z, cudaFuncAttributeMaxDynamicSharedMemorySize, KZ_SMEM);
        cudaStreamCreateWithFlags(&s2, cudaStreamNonBlocking);
        cudaEventCreateWithFlags(&evF, cudaEventDisableTiming);
        cudaEventCreateWithFlags(&evJ, cudaEventDisableTiming);
    }

    // fork: CSR chain (dst only) runs parallel to the GEMM chain
    cudaEventRecord(evF, 0);
    cudaStreamWaitEvent(s2, evF, 0);
    k_hist<<<(EE / 4 + 255) / 256, 256, 0, s2>>>(dst);
    k_scan<<<1, SCAN_T, 0, s2>>>();
    cudaEventRecord(evJ, s2);

    k_init<<<17, 256>>>(fc_w, edge_fc_w, edge_fc_b, attn_w);
    k_z<<<(NN + 127) / 128, 256, KZ_SMEM>>>(node_h, attn_w);

    // join: k_edge needs g_cur (scan) + g_s/g_d (k_z) + g_we (k_init)
    cudaStreamWaitEvent(0, evJ, 0);
    k_edge<<<(EE + 31) / 32, 256>>>(edge_h, src, dst);
    k_agg<<<(NN * 32 + 255) / 256, 256>>>(node_h, out);
}